// round 12
// baseline (speedup 1.0000x reference)
#include <cuda_runtime.h>
#include <cstdint>

// ---------------------------------------------------------------------------
// DCNv2, all-tensor-core INT8 (two-level quantization, 3-pass IMMA):
//  absmax     : deterministic abs-max of x / reg_w / (off_w,mod_w)
//  xt_kernel  : x NCHW -> [b][pix][ch] packed int8 pairs (q1 | q2<<8)
//  wq/w27q    : weights -> int8 two-level, k reordered to tap*256+c1
//  offmod_imma: 27-ch conv on IMMA -> offsets (clip) + masks (sigmoid)
//  dconv_imma : deformable implicit GEMM on IMMA, double-buffered pipeline
// GEMM view: M=C2=256, N=B*H*W=32768, K=2304, k = tap*256 + c1
// NOTE: aarch64 host -> plain `char` is UNSIGNED in device code too; all
// int8 arithmetic must go through `signed char`.
// ---------------------------------------------------------------------------

#define Bsz   8
#define C1    256
#define C2    256
#define Hd    64
#define Wd    64
#define HW    4096
#define KTOT  2304

typedef signed char s8;

__device__ unsigned g_maxb[3];   // bits of xmax, wmax, w27max (atomicMax, determ.)
__device__ __align__(16) unsigned short g_xq[(size_t)Bsz * HW * C1];
__device__ __align__(16) s8 g_wa1[C2 * KTOT];
__device__ __align__(16) s8 g_wa2[C2 * KTOT];
__device__ __align__(16) s8 g_w27a1[32 * KTOT];
__device__ __align__(16) s8 g_w27a2[32 * KTOT];
__device__ float g_offset[Bsz * 18 * HW];
__device__ float g_mask  [Bsz * 9  * HW];

// ---------------- helpers ---------------------------------------------------
__device__ __forceinline__ uint32_t smem_u32(const void* p) {
    uint32_t a;
    asm("{ .reg .u64 t; cvta.to.shared.u64 t, %1; cvt.u32.u64 %0, t; }"
        : "=r"(a) : "l"(p));
    return a;
}
__device__ __forceinline__ void ldm_x4(uint32_t* r, uint32_t a) {
    asm volatile("ldmatrix.sync.aligned.m8n8.x4.shared.b16 {%0,%1,%2,%3}, [%4];"
                 : "=r"(r[0]), "=r"(r[1]), "=r"(r[2]), "=r"(r[3]) : "r"(a));
}
__device__ __forceinline__ void ldm_x2(uint32_t* r, uint32_t a) {
    asm volatile("ldmatrix.sync.aligned.m8n8.x2.shared.b16 {%0,%1}, [%2];"
                 : "=r"(r[0]), "=r"(r[1]) : "r"(a));
}
__device__ __forceinline__ void imma(int* d, const uint32_t* a, const uint32_t* b) {
    asm volatile(
        "mma.sync.aligned.m16n8k32.row.col.s32.s8.s8.s32 "
        "{%0,%1,%2,%3}, {%4,%5,%6,%7}, {%8,%9}, {%0,%1,%2,%3};"
        : "+r"(d[0]), "+r"(d[1]), "+r"(d[2]), "+r"(d[3])
        : "r"(a[0]), "r"(a[1]), "r"(a[2]), "r"(a[3]), "r"(b[0]), "r"(b[1]));
}
__device__ __forceinline__ int q_clamp(int v) {
    return max(-127, min(127, v));
}
__device__ __forceinline__ float sb2f(unsigned q) {       // low byte, signed
    return (float)(int)(s8)(q & 0xffu);
}
__device__ __forceinline__ float sb2f_hi(unsigned q) {    // high byte, signed
    return (float)(int)(s8)((q >> 8) & 0xffu);
}

// ---------------------------------------------------------------------------
// abs-max reduction (order-independent -> deterministic, idempotent)
// ---------------------------------------------------------------------------
__global__ void absmax_kernel(const float* __restrict__ p, int n, int slot) {
    float m = 0.f;
    for (int i = blockIdx.x * blockDim.x + threadIdx.x; i < n;
         i += gridDim.x * blockDim.x)
        m = fmaxf(m, fabsf(p[i]));
#pragma unroll
    for (int o = 16; o; o >>= 1) m = fmaxf(m, __shfl_xor_sync(~0u, m, o));
    if ((threadIdx.x & 31) == 0) atomicMax(&g_maxb[slot], __float_as_uint(m));
}

// ---------------------------------------------------------------------------
// x NCHW -> [b][pix][ch] packed two-level int8
// ---------------------------------------------------------------------------
__global__ void xt_kernel(const float* __restrict__ x) {
    __shared__ float xs[32 * 129];
    int tid = threadIdx.x;
    int pb = blockIdx.x, cb = blockIdx.y, b = blockIdx.z;
    int pix0 = pb << 7, c0 = cb << 5;
#pragma unroll
    for (int j = 0; j < 16; ++j) {
        int idx = tid + (j << 8);
        int ci = idx >> 7, pi = idx & 127;
        xs[ci * 129 + pi] = x[((size_t)(b * C1 + c0 + ci) << 12) + pix0 + pi];
    }
    __syncthreads();
    float xmax = __uint_as_float(g_maxb[0]);
    float inv1 = 127.f / xmax, s1 = xmax * (1.f / 127.f);
    int lane = tid & 31, wid = tid >> 5;
#pragma unroll
    for (int j = 0; j < 16; ++j) {
        int pix = wid * 16 + j;
        float v = xs[lane * 129 + pix];
        int i1 = q_clamp(__float2int_rn(v * inv1));
        float r = v - (float)i1 * s1;
        int i2 = q_clamp(__float2int_rn(r * inv1 * 127.f));
        size_t o = ((size_t)((b << 12) + pix0 + pix) << 8) + c0 + lane;
        g_xq[o] = (unsigned short)((i1 & 0xff) | ((i2 & 0xff) << 8));
    }
}

// ---------------------------------------------------------------------------
// reg_w -> two-level int8, k -> tap*256 + c1
// ---------------------------------------------------------------------------
__global__ void wq_kernel(const float* __restrict__ regw) {
    int idx = blockIdx.x * 1024 + threadIdx.x;
    if (idx >= C2 * KTOT) return;
    float wmax = __uint_as_float(g_maxb[1]);
    float inv1 = 127.f / wmax, s1 = wmax * (1.f / 127.f);
    int c2 = idx / KTOT;
    int r  = idx - c2 * KTOT;     // c1*9 + tap
    int c1 = r / 9, tap = r - c1 * 9;
    float v = regw[idx];
    int i1 = q_clamp(__float2int_rn(v * inv1));
    float rr = v - (float)i1 * s1;
    int i2 = q_clamp(__float2int_rn(rr * inv1 * 127.f));
    int ko = c2 * KTOT + tap * 256 + c1;
    g_wa1[ko] = (s8)i1;
    g_wa2[ko] = (s8)i2;
}

__global__ void w27q_kernel(const float* __restrict__ offw,
                            const float* __restrict__ modw) {
    int idx = blockIdx.x * 256 + threadIdx.x;
    if (idx >= 32 * KTOT) return;
    float wmax = __uint_as_float(g_maxb[2]);
    float inv1 = 127.f / wmax, s1 = wmax * (1.f / 127.f);
    int m = idx / KTOT, k = idx - m * KTOT;
    int tap = k >> 8, c1 = k & 255;
    float v = 0.f;
    if (m < 18)      v = offw[(m * C1 + c1) * 9 + tap];
    else if (m < 27) v = modw[((m - 18) * C1 + c1) * 9 + tap];
    int i1 = q_clamp(__float2int_rn(v * inv1));
    float rr = v - (float)i1 * s1;
    int i2 = q_clamp(__float2int_rn(rr * inv1 * 127.f));
    g_w27a1[idx] = (s8)i1;
    g_w27a2[idx] = (s8)i2;
}

// ---------------------------------------------------------------------------
// offset+mask conv on IMMA: M=32(27), N=64 px (one row)/CTA, K=2304.
// B tiles are direct int8 byte copies (im2col shifts of g_xq).
// ---------------------------------------------------------------------------
__global__ __launch_bounds__(256)
void offmod_imma(const float* __restrict__ offb, const float* __restrict__ modb) {
    __shared__ __align__(16) s8 sm[9216];
    // A1 0 (1536), A2 1536, B1 3072 (3072), B2 6144
    uint32_t sb = smem_u32(sm);
    int tid = threadIdx.x, lane = tid & 31, wid = tid >> 5;
    int bx = blockIdx.x;
    int b = bx >> 6, h0 = bx & 63, pix0 = h0 << 6;

    int acch[2][4] = {{0}}, accx[2][4] = {{0}};
    const unsigned short* xqb = g_xq + ((size_t)b << 20);

    for (int c = 0; c < 72; ++c) {
        int tap = c >> 3, c1b = (c & 7) << 5;
        int kbase = tap * 256 + c1b;
        int dy = tap / 3 - 1, dx = tap % 3 - 1;
        __syncthreads();
        if (tid < 128) {          // A tiles: 32 rows x 32B x {a1,a2}
            int which = tid >> 6, rr = (tid & 63) >> 1, hf = tid & 1;
            const s8* src = (which ? g_w27a2 : g_w27a1)
                          + (size_t)rr * KTOT + kbase + hf * 16;
            *(uint4*)(sm + which * 1536 + rr * 48 + hf * 16) = *(const uint4*)src;
        }
        {                         // B tiles: byte copies with boundary zeros
            int sy = h0 + dy;
#pragma unroll
            for (int i = 0; i < 8; ++i) {
                int n = wid * 8 + i;
                int sx = n + dx;
                s8 q1 = 0, q2 = 0;
                if ((unsigned)sy < 64u && (unsigned)sx < 64u) {
                    unsigned q = xqb[((size_t)((sy << 6) + sx) << 8) + c1b + lane];
                    q1 = (s8)(q & 0xffu);
                    q2 = (s8)((q >> 8) & 0xffu);
                }
                sm[3072 + n * 48 + lane] = q1;
                sm[6144 + n * 48 + lane] = q2;
            }
        }
        __syncthreads();

        int lr = lane & 15, ls = lane >> 4;
        int br = lane & 7,  bs = (lane >> 3) & 1;
        uint32_t b1f[2], b2f[2];
        uint32_t ba = sb + 3072 + (wid * 8 + br) * 48 + bs * 16;
        ldm_x2(b1f, ba);
        ldm_x2(b2f, ba + 3072);
#pragma unroll
        for (int fm = 0; fm < 2; ++fm) {
            uint32_t a1[4], a2[4];
            uint32_t aa = sb + (fm * 16 + lr) * 48 + ls * 16;
            ldm_x4(a1, aa);
            ldm_x4(a2, aa + 1536);
            imma(acch[fm], a1, b1f);
            imma(accx[fm], a1, b2f);
            imma(accx[fm], a2, b1f);
        }
    }

    float xmax = __uint_as_float(g_maxb[0]);
    float wmax = __uint_as_float(g_maxb[2]);
    float s1 = (wmax * (1.f / 127.f)) * (xmax * (1.f / 127.f));
    float s2 = s1 * (1.f / 127.f);
#pragma unroll
    for (int fm = 0; fm < 2; ++fm)
#pragma unroll
        for (int half = 0; half < 2; ++half) {
            int r = fm * 16 + (lane >> 2) + half * 8;
            float v0 = s1 * (float)acch[fm][half * 2]     + s2 * (float)accx[fm][half * 2];
            float v1 = s1 * (float)acch[fm][half * 2 + 1] + s2 * (float)accx[fm][half * 2 + 1];
            int pix = pix0 + wid * 8 + ((lane & 3) << 1);
            if (r < 18) {
                float bb = __ldg(&offb[r]);
                v0 = fminf(fmaxf(v0 + bb, -16.f), 16.f);
                v1 = fminf(fmaxf(v1 + bb, -16.f), 16.f);
                *(float2*)&g_offset[((size_t)(b * 18 + r) << 12) + pix] =
                    make_float2(v0, v1);
            } else if (r < 27) {
                float bb = __ldg(&modb[r - 18]);
                v0 = 1.f / (1.f + __expf(-(v0 + bb)));
                v1 = 1.f / (1.f + __expf(-(v1 + bb)));
                *(float2*)&g_mask[((size_t)(b * 9 + r - 18) << 12) + pix] =
                    make_float2(v0, v1);
            }
        }
}

// ---------------------------------------------------------------------------
// Deformable implicit GEMM on IMMA. BM=128, BN=64 (one row), BK=32 (one tap,
// 32 ch). Bilinear gather from packed int8 corner pairs; re-quantized inline.
// Double-buffered, one sync per chunk.
// ---------------------------------------------------------------------------
#define ST_A1 0
#define ST_A2 6144
#define ST_B1 12288
#define ST_B2 15360
#define STAGE 18432
#define OFF_PW 36864           // float4[576] = 9216
#define OFF_PI 46080           // uint2 [576] = 4608
#define SMEM_DYN 50688

__global__ __launch_bounds__(256, 2)
void dconv_imma(float* __restrict__ out) {
    extern __shared__ s8 smem[];
    uint32_t sb = smem_u32(smem);
    float4* Pw = (float4*)(smem + OFF_PW);
    uint2*  Pi = (uint2*)(smem + OFF_PI);

    int tid = threadIdx.x, lane = tid & 31, wid = tid >> 5;
    int mw = wid >> 2, nw = wid & 3;          // warp tile 64m x 16n

    int bx = blockIdx.x;
    int b = bx >> 6, h0 = bx & 63, pix0 = h0 << 6;
    int c2_0 = blockIdx.y << 7;

    // ---- bilinear params: 9 taps x 64 positions ----
    for (int idx = tid; idx < 576; idx += 256) {
        int tap = idx >> 6, n = idx & 63;
        int w = n;
        int pix = pix0 + n;
        int obase = ((b * 18 + tap * 2) << 12) + pix;
        float dy = g_offset[obase];
        float dx = g_offset[obase + 4096];
        float m  = g_mask[((b * 9 + tap) << 12) + pix];
        float py = dy + (float)(tap / 3 + h0 - 1);
        float px = dx + (float)(tap % 3 + w - 1);
        float y0f = floorf(py), x0f = floorf(px);
        float ly = py - y0f, lx = px - x0f;
        int y0 = (int)y0f, x0 = (int)x0f;
        int y1 = y0 + 1,   x1 = x0 + 1;
        float vy0 = (y0 >= 0 && y0 < Hd) ? m : 0.f;
        float vy1 = (y1 >= 0 && y1 < Hd) ? m : 0.f;
        float vx0 = (x0 >= 0 && x0 < Wd) ? 1.f : 0.f;
        float vx1 = (x1 >= 0 && x1 < Wd) ? 1.f : 0.f;
        float4 wv;
        wv.x = (1.f - ly) * (1.f - lx) * vy0 * vx0;
        wv.y = (1.f - ly) * lx         * vy0 * vx1;
        wv.z = ly         * (1.f - lx) * vy1 * vx0;
        wv.w = ly         * lx         * vy1 * vx1;
        int cy0 = min(max(y0, 0), Hd - 1) << 6;
        int cy1 = min(max(y1, 0), Hd - 1) << 6;
        int cx0 = min(max(x0, 0), Wd - 1);
        int cx1 = min(max(x1, 0), Wd - 1);
        uint2 pk;
        pk.x = (unsigned)(cy0 + cx0) | ((unsigned)(cy0 + cx1) << 16);
        pk.y = (unsigned)(cy1 + cx0) | ((unsigned)(cy1 + cx1) << 16);
        Pw[idx] = wv;
        Pi[idx] = pk;
    }
    __syncthreads();

    int acch[4][2][4], accx[4][2][4];
#pragma unroll
    for (int i = 0; i < 4; ++i)
#pragma unroll
        for (int j = 0; j < 2; ++j)
#pragma unroll
            for (int q = 0; q < 4; ++q) { acch[i][j][q] = 0; accx[i][j][q] = 0; }

    const unsigned short* xqb = g_xq + ((size_t)b << 20);
    int arow = tid >> 1, ahf = tid & 1;

    // ---- prologue: build chunk 0 into stage 0 ----
    {
        *(uint4*)(smem + ST_A1 + arow * 48 + ahf * 16) =
            *(const uint4*)(g_wa1 + (size_t)(c2_0 + arow) * KTOT + ahf * 16);
        *(uint4*)(smem + ST_A2 + arow * 48 + ahf * 16) =
            *(const uint4*)(g_wa2 + (size_t)(c2_0 + arow) * KTOT + ahf * 16);
        const unsigned short* p = xqb + lane;
#pragma unroll
        for (int i = 0; i < 8; ++i) {
            int n = wid * 8 + i;
            float4 wv = Pw[n];
            uint2  pk = Pi[n];
            unsigned q00 = p[(size_t)(pk.x & 0xFFFFu) << 8];
            unsigned q01 = p[(size_t)(pk.x >> 16) << 8];
            unsigned q10 = p[(size_t)(pk.y & 0xFFFFu) << 8];
            unsigned q11 = p[(size_t)(pk.y >> 16) << 8];
            float u1 = wv.x * sb2f(q00) + wv.y * sb2f(q01)
                     + wv.z * sb2f(q10) + wv.w * sb2f(q11);
            float u2 = wv.x * sb2f_hi(q00) + wv.y * sb2f_hi(q01)
                     + wv.z * sb2f_hi(q10) + wv.w * sb2f_hi(q11);
            int b1 = __float2int_rn(u1);
            int b2 = q_clamp(__float2int_rn((u1 - (float)b1) * 127.f + u2));
            smem[ST_B1 + n * 48 + lane] = (s8)b1;
            smem[ST_B2 + n * 48 + lane] = (s8)b2;
        }
    }
    __syncthreads();

    int lr = lane & 15, ls = lane >> 4;
    int br = lane & 7,  bs = (lane >> 3) & 1;

    for (int c = 0; c < 72; ++c) {
        uint32_t scur = sb + ((c & 1) ? STAGE : 0);
        s8* tnxt = smem + (((c + 1) & 1) ? STAGE : 0);
        bool hasNext = (c + 1) < 72;
        int cn = c + 1, tapn = cn >> 3, c1bn = (cn & 7) << 5;
        float u1[8], u2[8];

        if (hasNext) {
            // A for chunk c+1 (stage free since last sync)
            int kb = tapn * 256 + c1bn;
            *(uint4*)(tnxt + ST_A1 + arow * 48 + ahf * 16) =
                *(const uint4*)(g_wa1 + (size_t)(c2_0 + arow) * KTOT + kb + ahf * 16);
            *(uint4*)(tnxt + ST_A2 + arow * 48 + ahf * 16) =
                *(const uint4*)(g_wa2 + (size_t)(c2_0 + arow) * KTOT + kb + ahf * 16);
            // B gather for chunk c+1
            const unsigned short* p = xqb + c1bn + lane;
#pragma unroll
            for (int i = 0; i < 8; ++i) {
                int n = wid * 8 + i;
                float4 wv = Pw[tapn * 64 + n];
                uint2  pk = Pi[tapn * 64 + n];
                unsigned q00 = p[(size_t)(pk.x & 0xFFFFu) << 8];
                unsigned q01 = p[(size_t)(pk.x >> 16) << 8];
                unsigned q10 = p[(size_t)(pk.y & 0xFFFFu) << 8];
                unsigned q11 = p[(size_t)(pk.y >> 16) << 8];
                u1[i] = wv.x * sb2f(q00) + wv.y * sb2f(q01)
                      + wv.z * sb2f(q10) + wv.w * sb2f(q11);
                u2[i] = wv.x * sb2f_hi(q00) + wv.y * sb2f_hi(q01)
                      + wv.z * sb2f_hi(q10) + wv.w * sb2f_hi(q11);
            }
        }

        // ---- mma on current stage ----
        uint32_t b1f[2][2], b2f[2][2];
#pragma unroll
        for (int fn = 0; fn < 2; ++fn) {
            uint32_t ba = scur + ST_B1 + (nw * 16 + fn * 8 + br) * 48 + bs * 16;
            ldm_x2(b1f[fn], ba);
            ldm_x2(b2f[fn], ba + (ST_B2 - ST_B1));
        }
#pragma unroll
        for (int fm = 0; fm < 4; ++fm) {
            uint32_t a1[4], a2[4];
            uint32_t aa = scur + ST_A1 + (mw * 64 + fm * 16 + lr) * 48 + ls * 16;
            ldm_x4(a1, aa);
            ldm_x4(a2, aa + (ST_A2 - ST_A1));
#pragma unroll
            for (int fn = 0; fn < 2; ++fn) {
                imma(acch[fm][fn], a1, b1f[fn]);
                imma(accx[fm][fn], a1, b2f[fn]);
                imma(accx[fm][fn], a2, b1f[fn]);
            }
        }

        if (hasNext) {
#pragma unroll
            for (int i = 0; i < 8; ++i) {
                int n = wid * 8 + i;
                int b1 = __float2int_rn(u1[i]);
                int b2 = q_clamp(__float2int_rn((u1[i] - (float)b1) * 127.f + u2[i]));
                tnxt[ST_B1 + n * 48 + lane] = (s8)b1;
                tnxt[ST_B2 + n * 48 + lane] = (s8)b2;
            }
        }
        __syncthreads();
    }

    // ---- epilogue ----
    float xmax = __uint_as_float(g_maxb[0]);
    float wmax = __uint_as_float(g_maxb[1]);
    float s1 = (wmax * (1.f / 127.f)) * (xmax * (1.f / 127.f));
    float s2 = s1 * (1.f / 127.f);
#pragma unroll
    for (int fm = 0; fm < 4; ++fm) {
#pragma unroll
        for (int fn = 0; fn < 2; ++fn) {
            int r0   = c2_0 + mw * 64 + fm * 16 + (lane >> 2);
            int ncol = pix0 + nw * 16 + fn * 8 + ((lane & 3) << 1);
            float* p0 = out + ((size_t)(b * C2 + r0) << 12) + ncol;
            float f0 = s1 * (float)acch[fm][fn][0] + s2 * (float)accx[fm][fn][0];
            float f1 = s1 * (float)acch[fm][fn][1] + s2 * (float)accx[fm][fn][1];
            float f2 = s1 * (float)acch[fm][fn][2] + s2 * (float)accx[fm][fn][2];
            float f3 = s1 * (float)acch[fm][fn][3] + s2 * (float)accx[fm][fn][3];
            *(float2*)p0 = make_float2(f0, f1);
            *(float2*)(p0 + (8u << 12)) = make_float2(f2, f3);
        }
    }
}

// ---------------------------------------------------------------------------
extern "C" void kernel_launch(void* const* d_in, const int* in_sizes, int n_in,
                              void* d_out, int out_size) {
    (void)in_sizes; (void)n_in; (void)out_size;
    const float* x    = (const float*)d_in[0];
    const float* offw = (const float*)d_in[1];
    const float* offb = (const float*)d_in[2];
    const float* modw = (const float*)d_in[3];
    const float* modb = (const float*)d_in[4];
    const float* regw = (const float*)d_in[5];
    float* out = (float*)d_out;

    cudaFuncSetAttribute(dconv_imma, cudaFuncAttributeMaxDynamicSharedMemorySize,
                         SMEM_DYN);
    absmax_kernel<<<512, 256>>>(x,    Bsz * C1 * HW, 0);
    absmax_kernel<<<128, 256>>>(regw, C2 * KTOT,     1);
    absmax_kernel<<<32,  256>>>(offw, 18 * C1 * 9,   2);
    absmax_kernel<<<16,  256>>>(modw, 9 * C1 * 9,    2);
    xt_kernel<<<dim3(32, 8, 8), 256>>>(x);
    wq_kernel<<<576, 1024>>>(regw);
    w27q_kernel<<<288, 256>>>(offw, modw);
    offmod_imma<<<512, 256>>>(offb, modb);
    dconv_imma<<<dim3(512, 2), 256, SMEM_DYN>>>(out);
}

// round 16
// speedup vs baseline: 2.0837x; 2.0837x over previous
#include <cuda_runtime.h>
#include <cuda_fp16.h>
#include <cstdint>

// ---------------------------------------------------------------------------
// DCNv2 via mma.sync fp16 2-pass (A-residual corrected, shared accumulator):
//  xt_kernel  : x NCHW -> HWC fp32 (dconv gather) + fp16 copy (offmod im2col)
//  wt_split   : reg_w -> fp16 AH + fp16 AL=(w-AH)*2048, k = tap*256 + c1
//  w27_split  : offset/mod weights -> same split, [32][2304]
//  offmod_mma : 27-ch conv on HMMA -> offsets (clip) + masks (sigmoid)
//  dconv_mma  : deformable implicit GEMM, double-buffered pipeline
// GEMM: M=C2=256, N=B*H*W=32768, K=2304, k = tap*256 + c1
// acc += AH*B + AL*Bs  with Bs = fp16(v/2048): scales cancel exactly.
// ---------------------------------------------------------------------------

#define Bsz   8
#define C1    256
#define C2    256
#define Hd    64
#define Wd    64
#define HW    4096
#define KTOT  2304

__device__ __align__(16) float  g_xt[(size_t)Bsz * HW * C1];   // [b][pix][c]
__device__ __align__(16) __half g_xh[(size_t)Bsz * HW * C1];
__device__ __align__(16) __half g_wh[C2 * KTOT];               // [c2][tap*256+c1]
__device__ __align__(16) __half g_wl[C2 * KTOT];               // residual * 2048
__device__ __align__(16) __half g_w27h[32 * KTOT];
__device__ __align__(16) __half g_w27l[32 * KTOT];
__device__ float g_offset[Bsz * 18 * HW];
__device__ float g_mask  [Bsz * 9  * HW];

// ---------------- helpers ---------------------------------------------------
__device__ __forceinline__ uint32_t smem_u32(const void* p) {
    uint32_t a;
    asm("{ .reg .u64 t; cvta.to.shared.u64 t, %1; cvt.u32.u64 %0, t; }"
        : "=r"(a) : "l"(p));
    return a;
}
__device__ __forceinline__ void ldm_x4(uint32_t* r, uint32_t a) {
    asm volatile("ldmatrix.sync.aligned.m8n8.x4.shared.b16 {%0,%1,%2,%3}, [%4];"
                 : "=r"(r[0]), "=r"(r[1]), "=r"(r[2]), "=r"(r[3]) : "r"(a));
}
__device__ __forceinline__ void ldm_x2(uint32_t* r, uint32_t a) {
    asm volatile("ldmatrix.sync.aligned.m8n8.x2.shared.b16 {%0,%1}, [%2];"
                 : "=r"(r[0]), "=r"(r[1]) : "r"(a));
}
__device__ __forceinline__ void mma_f16(float* d, const uint32_t* a,
                                        const uint32_t* b) {
    asm volatile(
        "mma.sync.aligned.m16n8k16.row.col.f32.f16.f16.f32 "
        "{%0,%1,%2,%3}, {%4,%5,%6,%7}, {%8,%9}, {%0,%1,%2,%3};"
        : "+f"(d[0]), "+f"(d[1]), "+f"(d[2]), "+f"(d[3])
        : "r"(a[0]), "r"(a[1]), "r"(a[2]), "r"(a[3]), "r"(b[0]), "r"(b[1]));
}

// ---------------------------------------------------------------------------
// K0: transpose x [B][C][HW] -> [B][HW][C] fp32 + fp16
// ---------------------------------------------------------------------------
__global__ void xt_kernel(const float* __restrict__ x) {
    __shared__ float xs[32 * 129];
    int tid = threadIdx.x;
    int pb = blockIdx.x, cb = blockIdx.y, b = blockIdx.z;
    int pix0 = pb << 7, c0 = cb << 5;
#pragma unroll
    for (int j = 0; j < 16; ++j) {
        int idx = tid + (j << 8);
        int ci = idx >> 7, pi = idx & 127;
        xs[ci * 129 + pi] = x[((size_t)(b * C1 + c0 + ci) << 12) + pix0 + pi];
    }
    __syncthreads();
    int lane = tid & 31, wid = tid >> 5;
#pragma unroll
    for (int j = 0; j < 16; ++j) {
        int pix = wid * 16 + j;
        float v = xs[lane * 129 + pix];
        size_t o = ((size_t)((b << 12) + pix0 + pix) << 8) + c0 + lane;
        g_xt[o] = v;
        g_xh[o] = __float2half_rn(v);
    }
}

// ---------------------------------------------------------------------------
// K1: reg_w -> fp16 AH + AL*2048, k -> tap*256 + c1
// ---------------------------------------------------------------------------
__global__ void wt_split_kernel(const float* __restrict__ regw) {
    int idx = blockIdx.x * 1024 + threadIdx.x;
    if (idx < C2 * KTOT) {
        int c2 = idx / KTOT;
        int r  = idx - c2 * KTOT;     // c1*9 + tap
        int c1 = r / 9, tap = r - c1 * 9;
        float v = regw[idx];
        __half hb = __float2half_rn(v);
        int ko = c2 * KTOT + tap * 256 + c1;
        g_wh[ko] = hb;
        g_wl[ko] = __float2half_rn((v - __half2float(hb)) * 2048.f);
    }
}

// ---------------------------------------------------------------------------
// K2: offset/mod weights -> fp16 split [32][tap*256+c1] (rows 27..31 = 0)
// ---------------------------------------------------------------------------
__global__ void w27_split_kernel(const float* __restrict__ offw,
                                 const float* __restrict__ modw) {
    int idx = blockIdx.x * 256 + threadIdx.x;
    if (idx >= 32 * KTOT) return;
    int m = idx / KTOT, k = idx - m * KTOT;
    int tap = k >> 8, c1 = k & 255;
    float v = 0.f;
    if (m < 18)      v = offw[(m * C1 + c1) * 9 + tap];
    else if (m < 27) v = modw[((m - 18) * C1 + c1) * 9 + tap];
    __half hb = __float2half_rn(v);
    g_w27h[idx] = hb;
    g_w27l[idx] = __float2half_rn((v - __half2float(hb)) * 2048.f);
}

// ---------------------------------------------------------------------------
// K3: offset+mask conv on HMMA fp16 2-pass: M=32(27), N=64 (one row)/CTA.
// B from g_xh (im2col shifts, coalesced); Bs = B/2048 computed inline.
// ---------------------------------------------------------------------------
#define ASTR 80
__global__ __launch_bounds__(256)
void offmod_mma(const float* __restrict__ offb, const float* __restrict__ modb) {
    // AH 0 (2560), AL 2560, B 5120 (5120), BS 10240 ; total 15360
    __shared__ __align__(16) char sm[15360];
    uint32_t sb = smem_u32(sm);
    int tid = threadIdx.x, lane = tid & 31, wid = tid >> 5;
    int bx = blockIdx.x;
    int b = bx >> 6, h0 = bx & 63, pix0 = h0 << 6;

    float acc[2][4] = {{0.f}};
    const __half* xhb = g_xh + ((size_t)b << 20);

    for (int c = 0; c < 72; ++c) {
        int tap = c >> 3, c1b = (c & 7) << 5;
        int kbase = tap * 256 + c1b;
        int dy = tap / 3 - 1, dx = tap % 3 - 1;
        __syncthreads();
        {   // A tiles: 2 x (32 rows x 64B)
            int which = tid >> 7, rem = tid & 127;
            int rr = rem >> 2, hf = rem & 3;
            const __half* src = (which ? g_w27l : g_w27h)
                              + (size_t)rr * KTOT + kbase + hf * 8;
            *(uint4*)(sm + which * 2560 + rr * ASTR + hf * 16) =
                *(const uint4*)src;
        }
        {   // B tiles: im2col fp16 + scaled copy
            int sy = h0 + dy;
#pragma unroll
            for (int i = 0; i < 8; ++i) {
                int n = wid * 8 + i;
                int sx = n + dx;
                __half h = __float2half_rn(0.f);
                if ((unsigned)sy < 64u && (unsigned)sx < 64u)
                    h = xhb[((size_t)((sy << 6) + sx) << 8) + c1b + lane];
                *(__half*)(sm + 5120  + n * ASTR + lane * 2) = h;
                *(__half*)(sm + 10240 + n * ASTR + lane * 2) =
                    __float2half_rn(__half2float(h) * (1.f / 2048.f));
            }
        }
        __syncthreads();

        int lr = lane & 15, ls = lane >> 4;
        int br = lane & 7,  bsel = (lane >> 3) & 1;
#pragma unroll
        for (int ks = 0; ks < 2; ++ks) {
            uint32_t bf[2], bsf[2];
            uint32_t ba = sb + 5120 + (wid * 8 + br) * ASTR + ks * 32 + bsel * 16;
            ldm_x2(bf, ba);
            ldm_x2(bsf, ba + 5120);
#pragma unroll
            for (int fm = 0; fm < 2; ++fm) {
                uint32_t ah[4], al[4];
                uint32_t aa = sb + (fm * 16 + lr) * ASTR + ks * 32 + ls * 16;
                ldm_x4(ah, aa);
                ldm_x4(al, aa + 2560);
                mma_f16(acc[fm], ah, bf);
                mma_f16(acc[fm], al, bsf);
            }
        }
    }

#pragma unroll
    for (int fm = 0; fm < 2; ++fm)
#pragma unroll
        for (int half = 0; half < 2; ++half) {
            int r = fm * 16 + (lane >> 2) + half * 8;
            float v0 = acc[fm][half * 2];
            float v1 = acc[fm][half * 2 + 1];
            int pix = pix0 + wid * 8 + ((lane & 3) << 1);
            if (r < 18) {
                float bb = __ldg(&offb[r]);
                v0 = fminf(fmaxf(v0 + bb, -16.f), 16.f);
                v1 = fminf(fmaxf(v1 + bb, -16.f), 16.f);
                *(float2*)&g_offset[((size_t)(b * 18 + r) << 12) + pix] =
                    make_float2(v0, v1);
            } else if (r < 27) {
                float bb = __ldg(&modb[r - 18]);
                v0 = 1.f / (1.f + __expf(-(v0 + bb)));
                v1 = 1.f / (1.f + __expf(-(v1 + bb)));
                *(float2*)&g_mask[((size_t)(b * 9 + r - 18) << 12) + pix] =
                    make_float2(v0, v1);
            }
        }
}

// ---------------------------------------------------------------------------
// K4: deformable implicit GEMM, fp16 2-pass, double-buffered pipeline.
// BM=128, BN=128 (2 rows), BK=32 (one tap, 32 ch). Gather from HWC fp32.
// ---------------------------------------------------------------------------
#define ST_AH 0
#define ST_AL 10240
#define ST_B  20480
#define ST_BS 30720
#define STAGE 40960
#define OFF_PW 81920          // float4[1152] = 18432
#define OFF_PI 100352         // uint2 [1152] =  9216
#define SMEM_DYN 109568

__global__ __launch_bounds__(256, 2)
void dconv_mma(float* __restrict__ out) {
    extern __shared__ char smem[];
    uint32_t sb = smem_u32(smem);
    float4* Pw = (float4*)(smem + OFF_PW);
    uint2*  Pi = (uint2*)(smem + OFF_PI);

    int tid = threadIdx.x, lane = tid & 31, wid = tid >> 5;
    int mw = wid >> 2, nw = wid & 3;

    int nt   = blockIdx.x;
    int b    = nt >> 5;
    int pix0 = (nt & 31) << 7;
    int h0   = pix0 >> 6;
    int c2_0 = blockIdx.y << 7;

    // ---- bilinear params: 9 taps x 128 positions ----
    for (int idx = tid; idx < 1152; idx += 256) {
        int tap = idx >> 7, n = idx & 127;
        int h = h0 + (n >> 6), w = n & 63;
        int pix   = (h << 6) + w;
        int obase = ((b * 18 + tap * 2) << 12) + pix;
        float dy = g_offset[obase];
        float dx = g_offset[obase + 4096];
        float m  = g_mask[((b * 9 + tap) << 12) + pix];
        float py = dy + (float)(tap / 3 + h - 1);
        float px = dx + (float)(tap % 3 + w - 1);
        float y0f = floorf(py), x0f = floorf(px);
        float ly = py - y0f, lx = px - x0f;
        int y0 = (int)y0f, x0 = (int)x0f;
        int y1 = y0 + 1,   x1 = x0 + 1;
        float vy0 = (y0 >= 0 && y0 < Hd) ? m : 0.f;
        float vy1 = (y1 >= 0 && y1 < Hd) ? m : 0.f;
        float vx0 = (x0 >= 0 && x0 < Wd) ? 1.f : 0.f;
        float vx1 = (x1 >= 0 && x1 < Wd) ? 1.f : 0.f;
        float4 wv;
        wv.x = (1.f - ly) * (1.f - lx) * vy0 * vx0;
        wv.y = (1.f - ly) * lx         * vy0 * vx1;
        wv.z = ly         * (1.f - lx) * vy1 * vx0;
        wv.w = ly         * lx         * vy1 * vx1;
        int cy0 = min(max(y0, 0), Hd - 1) << 6;
        int cy1 = min(max(y1, 0), Hd - 1) << 6;
        int cx0 = min(max(x0, 0), Wd - 1);
        int cx1 = min(max(x1, 0), Wd - 1);
        uint2 pk;
        pk.x = (unsigned)(cy0 + cx0) | ((unsigned)(cy0 + cx1) << 16);
        pk.y = (unsigned)(cy1 + cx0) | ((unsigned)(cy1 + cx1) << 16);
        Pw[idx] = wv;
        Pi[idx] = pk;
    }
    __syncthreads();

    float acc[4][4][4];
#pragma unroll
    for (int i = 0; i < 4; ++i)
#pragma unroll
        for (int j = 0; j < 4; ++j)
#pragma unroll
            for (int q = 0; q < 4; ++q) acc[i][j][q] = 0.f;

    const float* xb = g_xt + ((size_t)b << 20);
    int am = tid >> 2, ag = tid & 3;           // A rows am, am+64; quad ag

    // ---- prologue: build chunk 0 into stage 0 ----
    {
        const __half* whp = g_wh + (size_t)c2_0 * KTOT;
        const __half* wlp = g_wl + (size_t)c2_0 * KTOT;
        *(uint4*)(smem + ST_AH + am * ASTR + ag * 16) =
            *(const uint4*)(whp + (size_t)am * KTOT + ag * 8);
        *(uint4*)(smem + ST_AH + (am + 64) * ASTR + ag * 16) =
            *(const uint4*)(whp + (size_t)(am + 64) * KTOT + ag * 8);
        *(uint4*)(smem + ST_AL + am * ASTR + ag * 16) =
            *(const uint4*)(wlp + (size_t)am * KTOT + ag * 8);
        *(uint4*)(smem + ST_AL + (am + 64) * ASTR + ag * 16) =
            *(const uint4*)(wlp + (size_t)(am + 64) * KTOT + ag * 8);
#pragma unroll
        for (int i = 0; i < 16; ++i) {
            int n = wid * 16 + i;
            float4 wv = Pw[n];
            uint2  pk = Pi[n];
            const float* p = xb + lane;
            float v = wv.x * p[(size_t)(pk.x & 0xFFFFu) << 8]
                    + wv.y * p[(size_t)(pk.x >> 16) << 8]
                    + wv.z * p[(size_t)(pk.y & 0xFFFFu) << 8]
                    + wv.w * p[(size_t)(pk.y >> 16) << 8];
            *(__half*)(smem + ST_B  + n * ASTR + lane * 2) = __float2half_rn(v);
            *(__half*)(smem + ST_BS + n * ASTR + lane * 2) =
                __float2half_rn(v * (1.f / 2048.f));
        }
    }
    __syncthreads();

    int lr = lane & 15, ls = lane >> 4;
    int br = lane & 7,  bsel = (lane >> 3) & 1;

    for (int c = 0; c < 72; ++c) {
        uint32_t scur = sb + ((c & 1) ? STAGE : 0);
        char* tnxt = smem + (((c + 1) & 1) ? STAGE : 0);
        bool hasNext = (c + 1) < 72;
        int cn = c + 1, tapn = cn >> 3, c1bn = (cn & 7) << 5;
        float u1[16];

        if (hasNext) {
            int kb = tapn * 256 + c1bn;
            const __half* whp = g_wh + (size_t)c2_0 * KTOT + kb;
            const __half* wlp = g_wl + (size_t)c2_0 * KTOT + kb;
            uint4 a0 = *(const uint4*)(whp + (size_t)am * KTOT + ag * 8);
            uint4 a1 = *(const uint4*)(whp + (size_t)(am + 64) * KTOT + ag * 8);
            uint4 a2 = *(const uint4*)(wlp + (size_t)am * KTOT + ag * 8);
            uint4 a3 = *(const uint4*)(wlp + (size_t)(am + 64) * KTOT + ag * 8);
            const float* p = xb + c1bn + lane;
#pragma unroll
            for (int i = 0; i < 16; ++i) {
                int n = wid * 16 + i;
                float4 wv = Pw[tapn * 128 + n];
                uint2  pk = Pi[tapn * 128 + n];
                u1[i] = wv.x * p[(size_t)(pk.x & 0xFFFFu) << 8]
                      + wv.y * p[(size_t)(pk.x >> 16) << 8]
                      + wv.z * p[(size_t)(pk.y & 0xFFFFu) << 8]
                      + wv.w * p[(size_t)(pk.y >> 16) << 8];
            }
            *(uint4*)(tnxt + ST_AH + am * ASTR + ag * 16) = a0;
            *(uint4*)(tnxt + ST_AH + (am + 64) * ASTR + ag * 16) = a1;
            *(uint4*)(tnxt + ST_AL + am * ASTR + ag * 16) = a2;
            *(uint4*)(tnxt + ST_AL + (am + 64) * ASTR + ag * 16) = a3;
        }

        // ---- mma on current stage: acc += AH*B + AL*Bs ----
#pragma unroll
        for (int ks = 0; ks < 2; ++ks) {
            uint32_t bf[4][2], bsf[4][2];
#pragma unroll
            for (int fn = 0; fn < 4; ++fn) {
                uint32_t ba = scur + ST_B + (nw * 32 + fn * 8 + br) * ASTR
                            + ks * 32 + bsel * 16;
                ldm_x2(bf[fn], ba);
                ldm_x2(bsf[fn], ba + (ST_BS - ST_B));
            }
#pragma unroll
            for (int fm = 0; fm < 4; ++fm) {
                uint32_t ah[4], al[4];
                uint32_t aa = scur + ST_AH + (mw * 64 + fm * 16 + lr) * ASTR
                            + ks * 32 + ls * 16;
                ldm_x4(ah, aa);
                ldm_x4(al, aa + (ST_AL - ST_AH));
#pragma unroll
                for (int fn = 0; fn < 4; ++fn) {
                    mma_f16(acc[fm][fn], ah, bf[fn]);
                    mma_f16(acc[fm][fn], al, bsf[fn]);
                }
            }
        }

        if (hasNext) {
#pragma unroll
            for (int i = 0; i < 16; ++i) {
                int n = wid * 16 + i;
                *(__half*)(tnxt + ST_B  + n * ASTR + lane * 2) =
                    __float2half_rn(u1[i]);
                *(__half*)(tnxt + ST_BS + n * ASTR + lane * 2) =
                    __float2half_rn(u1[i] * (1.f / 2048.f));
            }
        }
        __syncthreads();
    }

    // ---- epilogue ----
#pragma unroll
    for (int fm = 0; fm < 4; ++fm) {
#pragma unroll
        for (int fn = 0; fn < 4; ++fn) {
            int r0   = c2_0 + mw * 64 + fm * 16 + (lane >> 2);
            int ncol = pix0 + nw * 32 + fn * 8 + ((lane & 3) << 1);
            float* p0 = out + ((size_t)(b * C2 + r0) << 12) + ncol;
            *(float2*)p0 = make_float2(acc[fm][fn][0], acc[fm][fn][1]);
            *(float2*)(p0 + (8u << 12)) = make_float2(acc[fm][fn][2], acc[fm][fn][3]);
        }
    }
}

// ---------------------------------------------------------------------------
extern "C" void kernel_launch(void* const* d_in, const int* in_sizes, int n_in,
                              void* d_out, int out_size) {
    (void)in_sizes; (void)n_in; (void)out_size;
    const float* x    = (const float*)d_in[0];
    const float* offw = (const float*)d_in[1];
    const float* offb = (const float*)d_in[2];
    const float* modw = (const float*)d_in[3];
    const float* modb = (const float*)d_in[4];
    const float* regw = (const float*)d_in[5];
    float* out = (float*)d_out;

    cudaFuncSetAttribute(dconv_mma, cudaFuncAttributeMaxDynamicSharedMemorySize,
                         SMEM_DYN);
    xt_kernel<<<dim3(32, 8, 8), 256>>>(x);
    wt_split_kernel<<<576, 1024>>>(regw);
    w27_split_kernel<<<288, 256>>>(offw, modw);
    offmod_mma<<<512, 256>>>(offb, modb);
    dconv_mma<<<dim3(256, 2), 256, SMEM_DYN>>>(out);
}

// round 17
// speedup vs baseline: 2.3077x; 1.1075x over previous
#include <cuda_runtime.h>
#include <cuda_fp16.h>
#include <cstdint>

// ---------------------------------------------------------------------------
// DCNv2 via mma.sync fp16 2-pass (A-residual corrected, shared accumulator):
//  xt_kernel  : x NCHW -> HWC fp32 (dconv gather) + fp16 copy (offmod im2col)
//  wt_split   : reg_w -> fp16 AH + fp16 AL=(w-AH)*2048, k = tap*256 + c1
//  w27_split  : offset/mod weights -> same split, [32][2304]
//  offmod_mma : 27-ch conv on HMMA (BK=64, half2 loads) -> offsets + masks
//  dconv_mma  : deformable implicit GEMM, double-buffered pipeline
// acc += AH*B + AL*(B*2^-11): second operand derived from the SAME B fragment
// via mul.f16x2 (no Bs smem tile).
// ---------------------------------------------------------------------------

#define Bsz   8
#define C1    256
#define C2    256
#define Hd    64
#define Wd    64
#define HW    4096
#define KTOT  2304

__device__ __align__(16) float  g_xt[(size_t)Bsz * HW * C1];   // [b][pix][c]
__device__ __align__(16) __half g_xh[(size_t)Bsz * HW * C1];
__device__ __align__(16) __half g_wh[C2 * KTOT];               // [c2][tap*256+c1]
__device__ __align__(16) __half g_wl[C2 * KTOT];               // residual * 2048
__device__ __align__(16) __half g_w27h[32 * KTOT];
__device__ __align__(16) __half g_w27l[32 * KTOT];
__device__ float g_offset[Bsz * 18 * HW];
__device__ float g_mask  [Bsz * 9  * HW];

// ---------------- helpers ---------------------------------------------------
__device__ __forceinline__ uint32_t smem_u32(const void* p) {
    uint32_t a;
    asm("{ .reg .u64 t; cvta.to.shared.u64 t, %1; cvt.u32.u64 %0, t; }"
        : "=r"(a) : "l"(p));
    return a;
}
__device__ __forceinline__ void ldm_x4(uint32_t* r, uint32_t a) {
    asm volatile("ldmatrix.sync.aligned.m8n8.x4.shared.b16 {%0,%1,%2,%3}, [%4];"
                 : "=r"(r[0]), "=r"(r[1]), "=r"(r[2]), "=r"(r[3]) : "r"(a));
}
__device__ __forceinline__ void ldm_x2(uint32_t* r, uint32_t a) {
    asm volatile("ldmatrix.sync.aligned.m8n8.x2.shared.b16 {%0,%1}, [%2];"
                 : "=r"(r[0]), "=r"(r[1]) : "r"(a));
}
__device__ __forceinline__ void mma_f16(float* d, const uint32_t* a,
                                        const uint32_t* b) {
    asm volatile(
        "mma.sync.aligned.m16n8k16.row.col.f32.f16.f16.f32 "
        "{%0,%1,%2,%3}, {%4,%5,%6,%7}, {%8,%9}, {%0,%1,%2,%3};"
        : "+f"(d[0]), "+f"(d[1]), "+f"(d[2]), "+f"(d[3])
        : "r"(a[0]), "r"(a[1]), "r"(a[2]), "r"(a[3]), "r"(b[0]), "r"(b[1]));
}
#define HSC 0x10001000u   // fp16x2 {2^-11, 2^-11}
__device__ __forceinline__ uint32_t hmul2(uint32_t a, uint32_t b) {
    uint32_t d;
    asm("mul.rn.f16x2 %0, %1, %2;" : "=r"(d) : "r"(a), "r"(b));
    return d;
}

// ---------------------------------------------------------------------------
// K0: transpose x [B][C][HW] -> [B][HW][C] fp32 + fp16
// ---------------------------------------------------------------------------
__global__ void xt_kernel(const float* __restrict__ x) {
    __shared__ float xs[32 * 129];
    int tid = threadIdx.x;
    int pb = blockIdx.x, cb = blockIdx.y, b = blockIdx.z;
    int pix0 = pb << 7, c0 = cb << 5;
#pragma unroll
    for (int j = 0; j < 16; ++j) {
        int idx = tid + (j << 8);
        int ci = idx >> 7, pi = idx & 127;
        xs[ci * 129 + pi] = x[((size_t)(b * C1 + c0 + ci) << 12) + pix0 + pi];
    }
    __syncthreads();
    int lane = tid & 31, wid = tid >> 5;
#pragma unroll
    for (int j = 0; j < 16; ++j) {
        int pix = wid * 16 + j;
        float v = xs[lane * 129 + pix];
        size_t o = ((size_t)((b << 12) + pix0 + pix) << 8) + c0 + lane;
        g_xt[o] = v;
        g_xh[o] = __float2half_rn(v);
    }
}

// ---------------------------------------------------------------------------
// K1: reg_w -> fp16 AH + AL*2048, k -> tap*256 + c1
// ---------------------------------------------------------------------------
__global__ void wt_split_kernel(const float* __restrict__ regw) {
    int idx = blockIdx.x * 1024 + threadIdx.x;
    if (idx < C2 * KTOT) {
        int c2 = idx / KTOT;
        int r  = idx - c2 * KTOT;     // c1*9 + tap
        int c1 = r / 9, tap = r - c1 * 9;
        float v = regw[idx];
        __half hb = __float2half_rn(v);
        int ko = c2 * KTOT + tap * 256 + c1;
        g_wh[ko] = hb;
        g_wl[ko] = __float2half_rn((v - __half2float(hb)) * 2048.f);
    }
}

// ---------------------------------------------------------------------------
// K2: offset/mod weights -> fp16 split [32][tap*256+c1] (rows 27..31 = 0)
// ---------------------------------------------------------------------------
__global__ void w27_split_kernel(const float* __restrict__ offw,
                                 const float* __restrict__ modw) {
    int idx = blockIdx.x * 256 + threadIdx.x;
    if (idx >= 32 * KTOT) return;
    int m = idx / KTOT, k = idx - m * KTOT;
    int tap = k >> 8, c1 = k & 255;
    float v = 0.f;
    if (m < 18)      v = offw[(m * C1 + c1) * 9 + tap];
    else if (m < 27) v = modw[((m - 18) * C1 + c1) * 9 + tap];
    __half hb = __float2half_rn(v);
    g_w27h[idx] = hb;
    g_w27l[idx] = __float2half_rn((v - __half2float(hb)) * 2048.f);
}

// ---------------------------------------------------------------------------
// K3: offset+mask conv on HMMA fp16 2-pass: M=32(27), N=64 (one row)/CTA,
// BK=64 (tap*256 + 64-ch group), half2 B loads, fragment-scaled pass 2.
// ---------------------------------------------------------------------------
#define ASTR2 144
__global__ __launch_bounds__(256)
void offmod_mma(const float* __restrict__ offb, const float* __restrict__ modb) {
    // AH 0 (4608), AL 4608 (4608), B 9216 (9216); total 18432
    __shared__ __align__(16) char sm[18432];
    uint32_t sb = smem_u32(sm);
    int tid = threadIdx.x, lane = tid & 31, wid = tid >> 5;
    int bx = blockIdx.x;
    int b = bx >> 6, h0 = bx & 63, pix0 = h0 << 6;

    float acc[2][4] = {{0.f}};
    const __half* xhb = g_xh + ((size_t)b << 20);

    int lr = lane & 15, ls = lane >> 4;
    int br = lane & 7,  bsel = (lane >> 3) & 1;
    int rr = tid >> 3, hf = tid & 7;

    for (int c = 0; c < 36; ++c) {
        int tap = c >> 2, c1b = (c & 3) << 6;
        int kbase = tap * 256 + c1b;
        int dy = tap / 3 - 1, dx = tap % 3 - 1;
        __syncthreads();
        {   // A tiles: 32 rows x 128B, both hi and lo
            *(uint4*)(sm + rr * ASTR2 + hf * 16) =
                *(const uint4*)(g_w27h + (size_t)rr * KTOT + kbase + hf * 8);
            *(uint4*)(sm + 4608 + rr * ASTR2 + hf * 16) =
                *(const uint4*)(g_w27l + (size_t)rr * KTOT + kbase + hf * 8);
        }
        {   // B tile: im2col half2 loads (4B per lane -> 128B/warp)
            int sy = h0 + dy;
#pragma unroll
            for (int i = 0; i < 8; ++i) {
                int n = wid * 8 + i;
                int sx = n + dx;
                unsigned q = 0;
                if ((unsigned)sy < 64u && (unsigned)sx < 64u)
                    q = *(const unsigned*)(xhb + ((size_t)((sy << 6) + sx) << 8)
                                           + c1b + lane * 2);
                *(unsigned*)(sm + 9216 + n * ASTR2 + lane * 4) = q;
            }
        }
        __syncthreads();

#pragma unroll
        for (int ks = 0; ks < 4; ++ks) {
            uint32_t bf[2], bsf[2];
            uint32_t ba = sb + 9216 + (wid * 8 + br) * ASTR2 + ks * 32 + bsel * 16;
            ldm_x2(bf, ba);
            bsf[0] = hmul2(bf[0], HSC);
            bsf[1] = hmul2(bf[1], HSC);
#pragma unroll
            for (int fm = 0; fm < 2; ++fm) {
                uint32_t ah[4], al[4];
                uint32_t aa = sb + (fm * 16 + lr) * ASTR2 + ks * 32 + ls * 16;
                ldm_x4(ah, aa);
                ldm_x4(al, aa + 4608);
                mma_f16(acc[fm], ah, bf);
                mma_f16(acc[fm], al, bsf);
            }
        }
    }

#pragma unroll
    for (int fm = 0; fm < 2; ++fm)
#pragma unroll
        for (int half = 0; half < 2; ++half) {
            int r = fm * 16 + (lane >> 2) + half * 8;
            float v0 = acc[fm][half * 2];
            float v1 = acc[fm][half * 2 + 1];
            int pix = pix0 + wid * 8 + ((lane & 3) << 1);
            if (r < 18) {
                float bb = __ldg(&offb[r]);
                v0 = fminf(fmaxf(v0 + bb, -16.f), 16.f);
                v1 = fminf(fmaxf(v1 + bb, -16.f), 16.f);
                *(float2*)&g_offset[((size_t)(b * 18 + r) << 12) + pix] =
                    make_float2(v0, v1);
            } else if (r < 27) {
                float bb = __ldg(&modb[r - 18]);
                v0 = 1.f / (1.f + __expf(-(v0 + bb)));
                v1 = 1.f / (1.f + __expf(-(v1 + bb)));
                *(float2*)&g_mask[((size_t)(b * 9 + r - 18) << 12) + pix] =
                    make_float2(v0, v1);
            }
        }
}

// ---------------------------------------------------------------------------
// K4: deformable implicit GEMM, fp16 2-pass, double-buffered pipeline.
// BM=128, BN=128 (2 rows), BK=32 (one tap, 32 ch). Gather from HWC fp32.
// Pass 2 B operand = fragment * 2^-11 (no Bs tile).
// ---------------------------------------------------------------------------
#define ASTR 80
#define ST_AH 0
#define ST_AL 10240
#define ST_B  20480
#define STAGE 30720
#define OFF_PW 61440          // float4[1152] = 18432
#define OFF_PI 79872          // uint2 [1152] =  9216
#define SMEM_DYN 89088

__global__ __launch_bounds__(256, 2)
void dconv_mma(float* __restrict__ out) {
    extern __shared__ char smem[];
    uint32_t sb = smem_u32(smem);
    float4* Pw = (float4*)(smem + OFF_PW);
    uint2*  Pi = (uint2*)(smem + OFF_PI);

    int tid = threadIdx.x, lane = tid & 31, wid = tid >> 5;
    int mw = wid >> 2, nw = wid & 3;

    int nt   = blockIdx.x;
    int b    = nt >> 5;
    int pix0 = (nt & 31) << 7;
    int h0   = pix0 >> 6;
    int c2_0 = blockIdx.y << 7;

    // ---- bilinear params: 9 taps x 128 positions ----
    for (int idx = tid; idx < 1152; idx += 256) {
        int tap = idx >> 7, n = idx & 127;
        int h = h0 + (n >> 6), w = n & 63;
        int pix   = (h << 6) + w;
        int obase = ((b * 18 + tap * 2) << 12) + pix;
        float dy = g_offset[obase];
        float dx = g_offset[obase + 4096];
        float m  = g_mask[((b * 9 + tap) << 12) + pix];
        float py = dy + (float)(tap / 3 + h - 1);
        float px = dx + (float)(tap % 3 + w - 1);
        float y0f = floorf(py), x0f = floorf(px);
        float ly = py - y0f, lx = px - x0f;
        int y0 = (int)y0f, x0 = (int)x0f;
        int y1 = y0 + 1,   x1 = x0 + 1;
        float vy0 = (y0 >= 0 && y0 < Hd) ? m : 0.f;
        float vy1 = (y1 >= 0 && y1 < Hd) ? m : 0.f;
        float vx0 = (x0 >= 0 && x0 < Wd) ? 1.f : 0.f;
        float vx1 = (x1 >= 0 && x1 < Wd) ? 1.f : 0.f;
        float4 wv;
        wv.x = (1.f - ly) * (1.f - lx) * vy0 * vx0;
        wv.y = (1.f - ly) * lx         * vy0 * vx1;
        wv.z = ly         * (1.f - lx) * vy1 * vx0;
        wv.w = ly         * lx         * vy1 * vx1;
        int cy0 = min(max(y0, 0), Hd - 1) << 6;
        int cy1 = min(max(y1, 0), Hd - 1) << 6;
        int cx0 = min(max(x0, 0), Wd - 1);
        int cx1 = min(max(x1, 0), Wd - 1);
        uint2 pk;
        pk.x = (unsigned)(cy0 + cx0) | ((unsigned)(cy0 + cx1) << 16);
        pk.y = (unsigned)(cy1 + cx0) | ((unsigned)(cy1 + cx1) << 16);
        Pw[idx] = wv;
        Pi[idx] = pk;
    }
    __syncthreads();

    float acc[4][4][4];
#pragma unroll
    for (int i = 0; i < 4; ++i)
#pragma unroll
        for (int j = 0; j < 4; ++j)
#pragma unroll
            for (int q = 0; q < 4; ++q) acc[i][j][q] = 0.f;

    const float* xb = g_xt + ((size_t)b << 20);
    int am = tid >> 2, ag = tid & 3;           // A rows am, am+64; quad ag

    // ---- prologue: build chunk 0 into stage 0 ----
    {
        const __half* whp = g_wh + (size_t)c2_0 * KTOT;
        const __half* wlp = g_wl + (size_t)c2_0 * KTOT;
        *(uint4*)(smem + ST_AH + am * ASTR + ag * 16) =
            *(const uint4*)(whp + (size_t)am * KTOT + ag * 8);
        *(uint4*)(smem + ST_AH + (am + 64) * ASTR + ag * 16) =
            *(const uint4*)(whp + (size_t)(am + 64) * KTOT + ag * 8);
        *(uint4*)(smem + ST_AL + am * ASTR + ag * 16) =
            *(const uint4*)(wlp + (size_t)am * KTOT + ag * 8);
        *(uint4*)(smem + ST_AL + (am + 64) * ASTR + ag * 16) =
            *(const uint4*)(wlp + (size_t)(am + 64) * KTOT + ag * 8);
#pragma unroll
        for (int i = 0; i < 16; ++i) {
            int n = wid * 16 + i;
            float4 wv = Pw[n];
            uint2  pk = Pi[n];
            const float* p = xb + lane;
            float v = wv.x * p[(size_t)(pk.x & 0xFFFFu) << 8]
                    + wv.y * p[(size_t)(pk.x >> 16) << 8]
                    + wv.z * p[(size_t)(pk.y & 0xFFFFu) << 8]
                    + wv.w * p[(size_t)(pk.y >> 16) << 8];
            *(__half*)(smem + ST_B + n * ASTR + lane * 2) = __float2half_rn(v);
        }
    }
    __syncthreads();

    int lr = lane & 15, ls = lane >> 4;
    int br = lane & 7,  bsel = (lane >> 3) & 1;

    for (int c = 0; c < 72; ++c) {
        uint32_t scur = sb + ((c & 1) ? STAGE : 0);
        char* tnxt = smem + (((c + 1) & 1) ? STAGE : 0);
        bool hasNext = (c + 1) < 72;
        int cn = c + 1, tapn = cn >> 3, c1bn = (cn & 7) << 5;
        float u1[16];

        if (hasNext) {
            int kb = tapn * 256 + c1bn;
            const __half* whp = g_wh + (size_t)c2_0 * KTOT + kb;
            const __half* wlp = g_wl + (size_t)c2_0 * KTOT + kb;
            uint4 a0 = *(const uint4*)(whp + (size_t)am * KTOT + ag * 8);
            uint4 a1 = *(const uint4*)(whp + (size_t)(am + 64) * KTOT + ag * 8);
            uint4 a2 = *(const uint4*)(wlp + (size_t)am * KTOT + ag * 8);
            uint4 a3 = *(const uint4*)(wlp + (size_t)(am + 64) * KTOT + ag * 8);
            const float* p = xb + c1bn + lane;
#pragma unroll
            for (int i = 0; i < 16; ++i) {
                int n = wid * 16 + i;
                float4 wv = Pw[tapn * 128 + n];
                uint2  pk = Pi[tapn * 128 + n];
                u1[i] = wv.x * p[(size_t)(pk.x & 0xFFFFu) << 8]
                      + wv.y * p[(size_t)(pk.x >> 16) << 8]
                      + wv.z * p[(size_t)(pk.y & 0xFFFFu) << 8]
                      + wv.w * p[(size_t)(pk.y >> 16) << 8];
            }
            *(uint4*)(tnxt + ST_AH + am * ASTR + ag * 16) = a0;
            *(uint4*)(tnxt + ST_AH + (am + 64) * ASTR + ag * 16) = a1;
            *(uint4*)(tnxt + ST_AL + am * ASTR + ag * 16) = a2;
            *(uint4*)(tnxt + ST_AL + (am + 64) * ASTR + ag * 16) = a3;
        }

        // ---- mma on current stage: acc += AH*B + AL*(B*2^-11) ----
#pragma unroll
        for (int ks = 0; ks < 2; ++ks) {
            uint32_t bf[4][2], bsf[4][2];
#pragma unroll
            for (int fn = 0; fn < 4; ++fn) {
                uint32_t ba = scur + ST_B + (nw * 32 + fn * 8 + br) * ASTR
                            + ks * 32 + bsel * 16;
                ldm_x2(bf[fn], ba);
                bsf[fn][0] = hmul2(bf[fn][0], HSC);
                bsf[fn][1] = hmul2(bf[fn][1], HSC);
            }
#pragma unroll
            for (int fm = 0; fm < 4; ++fm) {
                uint32_t ah[4], al[4];
                uint32_t aa = scur + ST_AH + (mw * 64 + fm * 16 + lr) * ASTR
                            + ks * 32 + ls * 16;
                ldm_x4(ah, aa);
                ldm_x4(al, aa + (ST_AL - ST_AH));
#pragma unroll
                for (int fn = 0; fn < 4; ++fn) {
                    mma_f16(acc[fm][fn], ah, bf[fn]);
                    mma_f16(acc[fm][fn], al, bsf[fn]);
                }
            }
        }

        if (hasNext) {
#pragma unroll
            for (int i = 0; i < 16; ++i) {
                int n = wid * 16 + i;
                *(__half*)(tnxt + ST_B + n * ASTR + lane * 2) =
                    __float2half_rn(u1[i]);
            }
        }
        __syncthreads();
    }

    // ---- epilogue ----
#pragma unroll
    for (int fm = 0; fm < 4; ++fm) {
#pragma unroll
        for (int fn = 0; fn < 4; ++fn) {
            int r0   = c2_0 + mw * 64 + fm * 16 + (lane >> 2);
            int ncol = pix0 + nw * 32 + fn * 8 + ((lane & 3) << 1);
            float* p0 = out + ((size_t)(b * C2 + r0) << 12) + ncol;
            *(float2*)p0 = make_float2(acc[fm][fn][0], acc[fm][fn][1]);
            *(float2*)(p0 + (8u << 12)) = make_float2(acc[fm][fn][2], acc[fm][fn][3]);
        }
    }
}

// ---------------------------------------------------------------------------
extern "C" void kernel_launch(void* const* d_in, const int* in_sizes, int n_in,
                              void* d_out, int out_size) {
    (void)in_sizes; (void)n_in; (void)out_size;
    const float* x    = (const float*)d_in[0];
    const float* offw = (const float*)d_in[1];
    const float* offb = (const float*)d_in[2];
    const float* modw = (const float*)d_in[3];
    const float* modb = (const float*)d_in[4];
    const float* regw = (const float*)d_in[5];
    float* out = (float*)d_out;

    cudaFuncSetAttribute(dconv_mma, cudaFuncAttributeMaxDynamicSharedMemorySize,
                         SMEM_DYN);
    xt_kernel<<<dim3(32, 8, 8), 256>>>(x);
    wt_split_kernel<<<576, 1024>>>(regw);
    w27_split_kernel<<<288, 256>>>(offw, modw);
    offmod_mma<<<512, 256>>>(offb, modb);
    dconv_mma<<<dim3(256, 2), 256, SMEM_DYN>>>(out);
}